// round 10
// baseline (speedup 1.0000x reference)
#include <cuda_runtime.h>
#include <cstddef>

// ---------------------------------------------------------------------------
// SLAYER SRM-alpha SNN — R1-bit-identical arithmetic.
// R10 = R4 smem-free scans/scanpool/dense + batch-paired conv:
// each conv thread computes 2 batch images x 8 channels x 4 t, halving
// weight-LDS wavefronts per FMA. Conv blocks at 256 threads (R3-proven).
// Layout [N,C,H,W,T], T innermost, T=300, N=8.
// ---------------------------------------------------------------------------

#define T_LEN  300
#define TC4    75
#define NBATCH 8

typedef unsigned long long ull;

#define C_DS 0.90483741803595952f     // exp(-1/10)
#define C_B  0.27182818284590452f     // e/10
#define C_DR 0.36787944117144233f     // exp(-1)
#define C_A  (-54.365636569180902f)   // -2*10*e
#define C_TH 10.0f
#define C_POOL 11.0f

#define BUF_ELEMS 30105600
__device__ float g_bufA[BUF_ELEMS + 16];
__device__ float g_bufB[BUF_ELEMS + 16];

__device__ __forceinline__ ull ffma2(ull a, ull b, ull c) {
    ull d;
    asm("fma.rn.f32x2 %0, %1, %2, %3;" : "=l"(d) : "l"(a), "l"(b), "l"(c));
    return d;
}

#define ELT(v, k) (((k) & 3) == 0 ? (v)[(k) >> 2].x : \
                   ((k) & 3) == 1 ? (v)[(k) >> 2].y : \
                   ((k) & 3) == 2 ? (v)[(k) >> 2].z : (v)[(k) >> 2].w)

// ---------------------------------------------------------------------------
// Temporal scan, smem-free. MODE: 0=psp, 1=spike+psp, 2=spike.
// ---------------------------------------------------------------------------
template<int CL, int MODE>
__device__ __forceinline__ void scan_tile(const float* __restrict__ xr,
                                          float* __restrict__ yr,
                                          float& p_s, float& q_s,
                                          float& p_r, float& q_r) {
    constexpr int NQ = CL / 4;
    float4 v[NQ];
    #pragma unroll
    for (int q = 0; q < NQ; q++) v[q] = *(const float4*)(xr + q * 4);
    float o[CL];
    #pragma unroll
    for (int k = 0; k < CL; k++) {
        float u = ELT(v, k);
        if (MODE == 0) {
            q_s = C_DS * (q_s + p_s);
            p_s = C_DS * p_s + u;
            o[k] = C_B * q_s;
        } else {
            q_r = C_DR * (q_r + p_r);
            float vm = u + C_A * q_r;
            float s = (vm >= C_TH) ? 1.0f : 0.0f;
            p_r = C_DR * p_r + s;
            if (MODE == 1) {
                q_s = C_DS * (q_s + p_s);
                p_s = C_DS * p_s + s;
                o[k] = C_B * q_s;
            } else {
                o[k] = s;
            }
        }
    }
    #pragma unroll
    for (int q = 0; q < NQ; q++)
        *(float4*)(yr + q * 4) =
            make_float4(o[q * 4], o[q * 4 + 1], o[q * 4 + 2], o[q * 4 + 3]);
}

template<int MODE>
__global__ __launch_bounds__(128)
void scan_t(const float* __restrict__ x, float* __restrict__ y,
            int numNeurons) {
    int gn = blockIdx.x * 128 + threadIdx.x;
    if (gn >= numNeurons) return;
    const float* xr = x + (size_t)gn * T_LEN;
    float*       yr = y + (size_t)gn * T_LEN;
    float p_s = 0.f, q_s = 0.f, p_r = 0.f, q_r = 0.f;
    #pragma unroll 1
    for (int tb = 0; tb < 288; tb += 16)
        scan_tile<16, MODE>(xr + tb, yr + tb, p_s, q_s, p_r, q_r);
    scan_tile<12, MODE>(xr + 288, yr + 288, p_s, q_s, p_r, q_r);
}

// ---------------------------------------------------------------------------
// Fused [spike+psp on 4 children] + 2x2 pool(*11) + [spike+psp], smem-free.
// ---------------------------------------------------------------------------
template<int CL>
__device__ __forceinline__ void pool_tile(
    const float* __restrict__ x0, const float* __restrict__ x1,
    const float* __restrict__ x2, const float* __restrict__ x3,
    float* __restrict__ yr,
    float* cpr, float* cqr, float* cps, float* cqs,
    float& Ppr, float& Pqr, float& Pps, float& Pqs) {
    constexpr int NQ = CL / 4;
    float4 v0[NQ], v1[NQ], v2[NQ], v3[NQ];
    #pragma unroll
    for (int q = 0; q < NQ; q++) v0[q] = *(const float4*)(x0 + q * 4);
    #pragma unroll
    for (int q = 0; q < NQ; q++) v1[q] = *(const float4*)(x1 + q * 4);
    #pragma unroll
    for (int q = 0; q < NQ; q++) v2[q] = *(const float4*)(x2 + q * 4);
    #pragma unroll
    for (int q = 0; q < NQ; q++) v3[q] = *(const float4*)(x3 + q * 4);
    float o[CL];
    #pragma unroll
    for (int k = 0; k < CL; k++) {
        float outc[4];
        #pragma unroll
        for (int c = 0; c < 4; c++) {
            float u = (c == 0) ? ELT(v0, k) : (c == 1) ? ELT(v1, k)
                    : (c == 2) ? ELT(v2, k) : ELT(v3, k);
            cqr[c] = C_DR * (cqr[c] + cpr[c]);
            float vm = u + C_A * cqr[c];
            float s  = (vm >= C_TH) ? 1.0f : 0.0f;
            cpr[c] = C_DR * cpr[c] + s;
            cqs[c] = C_DS * (cqs[c] + cps[c]);
            cps[c] = C_DS * cps[c] + s;
            outc[c] = C_B * cqs[c];
        }
        float U = (outc[0] + outc[1] + outc[2] + outc[3]) * C_POOL;
        Pqr = C_DR * (Pqr + Ppr);
        float vm = U + C_A * Pqr;
        float s  = (vm >= C_TH) ? 1.0f : 0.0f;
        Ppr = C_DR * Ppr + s;
        Pqs = C_DS * (Pqs + Pps);
        Pps = C_DS * Pps + s;
        o[k] = C_B * Pqs;
    }
    #pragma unroll
    for (int q = 0; q < NQ; q++)
        *(float4*)(yr + q * 4) =
            make_float4(o[q * 4], o[q * 4 + 1], o[q * 4 + 2], o[q * 4 + 3]);
}

__global__ __launch_bounds__(128)
void scanpool2x(const float* __restrict__ x, float* __restrict__ y,
                int C, int OH, int OW) {
    const int gn = blockIdx.x * 128 + threadIdx.x;
    int ox = gn % OW; int r = gn / OW;
    int oy = r % OH;  r /= OH;
    int c  = r % C;   int n = r / C;
    const int W = OW * 2, H = OH * 2;
    size_t base = (((size_t)(n * C + c) * H + 2 * oy) * W + 2 * ox) * T_LEN;
    const float* x0 = x + base;
    const float* x1 = x + base + T_LEN;
    const float* x2 = x + base + (size_t)W * T_LEN;
    const float* x3 = x + base + (size_t)(W + 1) * T_LEN;
    float* yr = y + (size_t)gn * T_LEN;

    float cpr[4] = {0,0,0,0}, cqr[4] = {0,0,0,0};
    float cps[4] = {0,0,0,0}, cqs[4] = {0,0,0,0};
    float Ppr = 0.f, Pqr = 0.f, Pps = 0.f, Pqs = 0.f;

    #pragma unroll 1
    for (int tb = 0; tb < 288; tb += 16)
        pool_tile<16>(x0 + tb, x1 + tb, x2 + tb, x3 + tb, yr + tb,
                      cpr, cqr, cps, cqs, Ppr, Pqr, Pps, Pqs);
    pool_tile<12>(x0 + 288, x1 + 288, x2 + 288, x3 + 288, yr + 288,
                  cpr, cqr, cps, cqs, Ppr, Pqr, Pps, Pqs);
}

// ---------------------------------------------------------------------------
// Batch-paired direct conv: thread = (n-pair, oy, ox, tc); computes
// 2 batches x CO_BLK channels x 4 t. Weight LDS amortized over both batches.
// Accumulation order per output value: (ci,kh,kw), R1-identical.
// ---------------------------------------------------------------------------
template<int CI, int CO, int CO_BLK, int K, int H, int W, int OH, int OW, int PAD>
__global__ __launch_bounds__(256)
void conv_nb2(const float* __restrict__ x, const float* __restrict__ wgt,
              float* __restrict__ y) {
    constexpr int TAPS = CI * K * K;
    __shared__ float2 ws[TAPS * CO_BLK];
    const int oBase = blockIdx.y * CO_BLK;
    for (int i = threadIdx.x; i < TAPS * CO_BLK; i += blockDim.x) {
        int o = i % CO_BLK, tap = i / CO_BLK;
        float v = wgt[(oBase + o) * TAPS + tap];
        ws[i] = make_float2(v, v);
    }
    __syncthreads();

    int g = blockIdx.x * blockDim.x + threadIdx.x;
    int tc = g % TC4; int r = g / TC4;
    int ox = r % OW; r /= OW;
    int oy = r % OH; r /= OH;
    int np = r;                          // batch pair 0..3
    if (np >= NBATCH / 2) return;
    const int n0 = np * 2;

    ulonglong2 acc0[CO_BLK], acc1[CO_BLK];
    #pragma unroll
    for (int o = 0; o < CO_BLK; o++) {
        acc0[o] = make_ulonglong2(0ULL, 0ULL);
        acc1[o] = make_ulonglong2(0ULL, 0ULL);
    }

    const size_t nstr = (size_t)CI * H * W * T_LEN;
    const float* xb0 = x + (size_t)n0 * nstr + tc * 4;
    const float* xb1 = xb0 + nstr;

    #pragma unroll 1
    for (int ci = 0; ci < CI; ci++) {
        #pragma unroll
        for (int kh = 0; kh < K; kh++) {
            int iy = oy + kh - PAD;
            if ((unsigned)iy >= (unsigned)H) continue;
            const size_t rowoff = (size_t)(ci * H + iy) * W * T_LEN;
            #pragma unroll
            for (int kw = 0; kw < K; kw++) {
                int ix = ox + kw - PAD;
                if ((unsigned)ix >= (unsigned)W) continue;
                const size_t off = rowoff + (size_t)ix * T_LEN;
                float4 f0 = *(const float4*)(xb0 + off);
                float4 f1 = *(const float4*)(xb1 + off);
                ulonglong2 xu0 = *(ulonglong2*)&f0;
                ulonglong2 xu1 = *(ulonglong2*)&f1;
                const float2* wrow = &ws[((ci * K + kh) * K + kw) * CO_BLK];
                #pragma unroll
                for (int o = 0; o < CO_BLK; o += 2) {
                    float4 wv = *(const float4*)(wrow + o);
                    ull w0 = ((ull*)&wv)[0];
                    ull w1 = ((ull*)&wv)[1];
                    acc0[o].x   = ffma2(w0, xu0.x, acc0[o].x);
                    acc0[o].y   = ffma2(w0, xu0.y, acc0[o].y);
                    acc1[o].x   = ffma2(w0, xu1.x, acc1[o].x);
                    acc1[o].y   = ffma2(w0, xu1.y, acc1[o].y);
                    acc0[o+1].x = ffma2(w1, xu0.x, acc0[o+1].x);
                    acc0[o+1].y = ffma2(w1, xu0.y, acc0[o+1].y);
                    acc1[o+1].x = ffma2(w1, xu1.x, acc1[o+1].x);
                    acc1[o+1].y = ffma2(w1, xu1.y, acc1[o+1].y);
                }
            }
        }
    }
    const size_t obase0 = (((size_t)(n0 * CO + oBase) * OH + oy) * OW + ox) * T_LEN
                          + tc * 4;
    const size_t ostr   = (size_t)CO * OH * OW * T_LEN;
    #pragma unroll
    for (int o = 0; o < CO_BLK; o++) {
        size_t off = obase0 + (size_t)o * OH * OW * T_LEN;
        *(ulonglong2*)(y + off)        = acc0[o];
        *(ulonglong2*)(y + off + ostr) = acc1[o];
    }
}

// ---------------------------------------------------------------------------
// Dense over (C,H,W)=3136 per timestep: [8,64,7,7,300] -> [8,10,300].
// Sequential i order preserved (feeds the final output spikes directly).
// ---------------------------------------------------------------------------
__global__ __launch_bounds__(256)
void dense_kernel(const float* __restrict__ x, const float* __restrict__ wgt,
                  float* __restrict__ y) {
    int g = blockIdx.x * blockDim.x + threadIdx.x;
    if (g >= NBATCH * 10 * T_LEN) return;
    int t = g % T_LEN; int r = g / T_LEN;
    int o = r % 10;    int n = r / 10;
    const float* xb = x + (size_t)n * 3136 * T_LEN + t;
    const float* wb = wgt + o * 3136;
    float acc = 0.f;
    #pragma unroll 16
    for (int i = 0; i < 3136; i++)
        acc = fmaf(wb[i], xb[(size_t)i * T_LEN], acc);
    y[g] = acc;
}

// ---------------------------------------------------------------------------

static inline int cdiv(long long a, long long b) { return (int)((a + b - 1) / b); }

extern "C" void kernel_launch(void* const* d_in, const int* in_sizes, int n_in,
                              void* d_out, int out_size) {
    const float* in = (const float*)d_in[0];   // [8,1,30,30,300]
    const float* w1 = (const float*)d_in[1];   // [16,1,5,5]
    const float* w2 = (const float*)d_in[2];   // [32,16,3,3]
    const float* w3 = (const float*)d_in[3];   // [64,32,3,3]
    const float* w4 = (const float*)d_in[4];   // [10,64,7,7]
    float* out = (float*)d_out;                // [8,10,300]

    float *bufA, *bufB;
    cudaGetSymbolAddress((void**)&bufA, g_bufA);
    cudaGetSymbolAddress((void**)&bufB, g_bufB);

    // P0 = psp(input)  [8,1,30,30,300]
    scan_t<0><<<cdiv(7200, 128), 128>>>(in, bufA, 7200);

    // u1 = conv1(P0)   [8,16,28,28,300]   (4 n-pairs, 2 ch-groups)
    conv_nb2<1, 16, 8, 5, 30, 30, 28, 28, 1>
        <<<dim3(cdiv((long long)(NBATCH / 2) * 28 * 28 * TC4, 256), 2), 256>>>(bufA, w1, bufB);

    // Q2 = psp(spike(pool(psp(spike(u1)))))  [8,16,14,14,300]
    scanpool2x<<<25088 / 128, 128>>>(bufB, bufA, 16, 14, 14);

    // u3 = conv2(Q2)   [8,32,14,14,300]   (4 n-pairs, 4 ch-groups)
    conv_nb2<16, 32, 8, 3, 14, 14, 14, 14, 1>
        <<<dim3(cdiv((long long)(NBATCH / 2) * 14 * 14 * TC4, 256), 4), 256>>>(bufA, w2, bufB);

    // Q4 = psp(spike(pool(psp(spike(u3)))))  [8,32,7,7,300]
    scanpool2x<<<12544 / 128, 128>>>(bufB, bufA, 32, 7, 7);

    // u5 = conv3(Q4)   [8,64,7,7,300]    (4 n-pairs, 8 ch-groups)
    conv_nb2<32, 64, 8, 3, 7, 7, 7, 7, 1>
        <<<dim3(cdiv((long long)(NBATCH / 2) * 7 * 7 * TC4, 256), 8), 256>>>(bufA, w3, bufB);

    // Q5 = psp(spike(u5))  [8,64,7,7,300]
    scan_t<1><<<cdiv(25088, 128), 128>>>(bufB, bufA, 25088);

    // u6 = dense(Q5)   [8,10,300]
    dense_kernel<<<cdiv(NBATCH * 10 * T_LEN, 256), 256>>>(bufA, w4, bufB);

    // out = spike(u6)
    scan_t<2><<<1, 128>>>(bufB, out, 80);
}

// round 12
// speedup vs baseline: 1.1965x; 1.1965x over previous
#include <cuda_runtime.h>
#include <cstddef>

// ---------------------------------------------------------------------------
// SLAYER SRM-alpha SNN — R1-bit-identical arithmetic.
// R11 = R4 smem-free scans/scanpool/dense + R3 conv (CO_BLK=16, 256thr) with
// boundary guards converted to predicated zero-fill loads (exact: fma(w,0)=acc)
// so all 9-18 LDGs per ci batch into one MLP group. launch_bounds(256,2).
// Layout [N,C,H,W,T], T innermost, T=300, N=8.
// ---------------------------------------------------------------------------

#define T_LEN  300
#define TC4    75
#define NBATCH 8

typedef unsigned long long ull;

#define C_DS 0.90483741803595952f     // exp(-1/10)
#define C_B  0.27182818284590452f     // e/10
#define C_DR 0.36787944117144233f     // exp(-1)
#define C_A  (-54.365636569180902f)   // -2*10*e
#define C_TH 10.0f
#define C_POOL 11.0f

#define BUF_ELEMS 30105600
__device__ float g_bufA[BUF_ELEMS + 16];
__device__ float g_bufB[BUF_ELEMS + 16];

__device__ __forceinline__ ull ffma2(ull a, ull b, ull c) {
    ull d;
    asm("fma.rn.f32x2 %0, %1, %2, %3;" : "=l"(d) : "l"(a), "l"(b), "l"(c));
    return d;
}

#define ELT(v, k) (((k) & 3) == 0 ? (v)[(k) >> 2].x : \
                   ((k) & 3) == 1 ? (v)[(k) >> 2].y : \
                   ((k) & 3) == 2 ? (v)[(k) >> 2].z : (v)[(k) >> 2].w)

// ---------------------------------------------------------------------------
// Temporal scan, smem-free. MODE: 0=psp, 1=spike+psp, 2=spike.
// ---------------------------------------------------------------------------
template<int CL, int MODE>
__device__ __forceinline__ void scan_tile(const float* __restrict__ xr,
                                          float* __restrict__ yr,
                                          float& p_s, float& q_s,
                                          float& p_r, float& q_r) {
    constexpr int NQ = CL / 4;
    float4 v[NQ];
    #pragma unroll
    for (int q = 0; q < NQ; q++) v[q] = *(const float4*)(xr + q * 4);
    float o[CL];
    #pragma unroll
    for (int k = 0; k < CL; k++) {
        float u = ELT(v, k);
        if (MODE == 0) {
            q_s = C_DS * (q_s + p_s);
            p_s = C_DS * p_s + u;
            o[k] = C_B * q_s;
        } else {
            q_r = C_DR * (q_r + p_r);
            float vm = u + C_A * q_r;
            float s = (vm >= C_TH) ? 1.0f : 0.0f;
            p_r = C_DR * p_r + s;
            if (MODE == 1) {
                q_s = C_DS * (q_s + p_s);
                p_s = C_DS * p_s + s;
                o[k] = C_B * q_s;
            } else {
                o[k] = s;
            }
        }
    }
    #pragma unroll
    for (int q = 0; q < NQ; q++)
        *(float4*)(yr + q * 4) =
            make_float4(o[q * 4], o[q * 4 + 1], o[q * 4 + 2], o[q * 4 + 3]);
}

template<int MODE>
__global__ __launch_bounds__(128)
void scan_t(const float* __restrict__ x, float* __restrict__ y,
            int numNeurons) {
    int gn = blockIdx.x * 128 + threadIdx.x;
    if (gn >= numNeurons) return;
    const float* xr = x + (size_t)gn * T_LEN;
    float*       yr = y + (size_t)gn * T_LEN;
    float p_s = 0.f, q_s = 0.f, p_r = 0.f, q_r = 0.f;
    #pragma unroll 1
    for (int tb = 0; tb < 288; tb += 16)
        scan_tile<16, MODE>(xr + tb, yr + tb, p_s, q_s, p_r, q_r);
    scan_tile<12, MODE>(xr + 288, yr + 288, p_s, q_s, p_r, q_r);
}

// ---------------------------------------------------------------------------
// Fused [spike+psp on 4 children] + 2x2 pool(*11) + [spike+psp], smem-free.
// ---------------------------------------------------------------------------
template<int CL>
__device__ __forceinline__ void pool_tile(
    const float* __restrict__ x0, const float* __restrict__ x1,
    const float* __restrict__ x2, const float* __restrict__ x3,
    float* __restrict__ yr,
    float* cpr, float* cqr, float* cps, float* cqs,
    float& Ppr, float& Pqr, float& Pps, float& Pqs) {
    constexpr int NQ = CL / 4;
    float4 v0[NQ], v1[NQ], v2[NQ], v3[NQ];
    #pragma unroll
    for (int q = 0; q < NQ; q++) v0[q] = *(const float4*)(x0 + q * 4);
    #pragma unroll
    for (int q = 0; q < NQ; q++) v1[q] = *(const float4*)(x1 + q * 4);
    #pragma unroll
    for (int q = 0; q < NQ; q++) v2[q] = *(const float4*)(x2 + q * 4);
    #pragma unroll
    for (int q = 0; q < NQ; q++) v3[q] = *(const float4*)(x3 + q * 4);
    float o[CL];
    #pragma unroll
    for (int k = 0; k < CL; k++) {
        float outc[4];
        #pragma unroll
        for (int c = 0; c < 4; c++) {
            float u = (c == 0) ? ELT(v0, k) : (c == 1) ? ELT(v1, k)
                    : (c == 2) ? ELT(v2, k) : ELT(v3, k);
            cqr[c] = C_DR * (cqr[c] + cpr[c]);
            float vm = u + C_A * cqr[c];
            float s  = (vm >= C_TH) ? 1.0f : 0.0f;
            cpr[c] = C_DR * cpr[c] + s;
            cqs[c] = C_DS * (cqs[c] + cps[c]);
            cps[c] = C_DS * cps[c] + s;
            outc[c] = C_B * cqs[c];
        }
        float U = (outc[0] + outc[1] + outc[2] + outc[3]) * C_POOL;
        Pqr = C_DR * (Pqr + Ppr);
        float vm = U + C_A * Pqr;
        float s  = (vm >= C_TH) ? 1.0f : 0.0f;
        Ppr = C_DR * Ppr + s;
        Pqs = C_DS * (Pqs + Pps);
        Pps = C_DS * Pps + s;
        o[k] = C_B * Pqs;
    }
    #pragma unroll
    for (int q = 0; q < NQ; q++)
        *(float4*)(yr + q * 4) =
            make_float4(o[q * 4], o[q * 4 + 1], o[q * 4 + 2], o[q * 4 + 3]);
}

__global__ __launch_bounds__(128)
void scanpool2x(const float* __restrict__ x, float* __restrict__ y,
                int C, int OH, int OW) {
    const int gn = blockIdx.x * 128 + threadIdx.x;
    int ox = gn % OW; int r = gn / OW;
    int oy = r % OH;  r /= OH;
    int c  = r % C;   int n = r / C;
    const int W = OW * 2, H = OH * 2;
    size_t base = (((size_t)(n * C + c) * H + 2 * oy) * W + 2 * ox) * T_LEN;
    const float* x0 = x + base;
    const float* x1 = x + base + T_LEN;
    const float* x2 = x + base + (size_t)W * T_LEN;
    const float* x3 = x + base + (size_t)(W + 1) * T_LEN;
    float* yr = y + (size_t)gn * T_LEN;

    float cpr[4] = {0,0,0,0}, cqr[4] = {0,0,0,0};
    float cps[4] = {0,0,0,0}, cqs[4] = {0,0,0,0};
    float Ppr = 0.f, Pqr = 0.f, Pps = 0.f, Pqs = 0.f;

    #pragma unroll 1
    for (int tb = 0; tb < 288; tb += 16)
        pool_tile<16>(x0 + tb, x1 + tb, x2 + tb, x3 + tb, yr + tb,
                      cpr, cqr, cps, cqs, Ppr, Pqr, Pps, Pqs);
    pool_tile<12>(x0 + 288, x1 + 288, x2 + 288, x3 + 288, yr + 288,
                  cpr, cqr, cps, cqs, Ppr, Pqr, Pps, Pqs);
}

// ---------------------------------------------------------------------------
// Direct conv, R3 blocking (CO_BLK=16, 256thr), boundary guards as
// PREDICATED zero-fill loads: fma(w, 0, acc) == acc exactly, so arithmetic
// is identical while the 9 (x UNR) loads per ci batch into one MLP group.
// Accumulation order per output value: (ci,kh,kw), R1-identical.
// ---------------------------------------------------------------------------
template<int CI, int CO, int CO_BLK, int K, int H, int W, int OH, int OW,
         int PAD, int UNR>
__global__ __launch_bounds__(256, 2)
void conv_kernel(const float* __restrict__ x, const float* __restrict__ wgt,
                 float* __restrict__ y) {
    constexpr int TAPS = CI * K * K;
    __shared__ float2 ws[TAPS * CO_BLK];
    const int oBase = blockIdx.y * CO_BLK;
    for (int i = threadIdx.x; i < TAPS * CO_BLK; i += blockDim.x) {
        int o = i % CO_BLK, tap = i / CO_BLK;
        float v = wgt[(oBase + o) * TAPS + tap];
        ws[i] = make_float2(v, v);
    }
    __syncthreads();

    long long g = (long long)blockIdx.x * blockDim.x + threadIdx.x;
    int tc = (int)(g % TC4); long long r = g / TC4;
    int ox = (int)(r % OW); r /= OW;
    int oy = (int)(r % OH); r /= OH;
    int n  = (int)r;
    if (n >= NBATCH) return;

    ulonglong2 acc[CO_BLK];
    #pragma unroll
    for (int o = 0; o < CO_BLK; o++) acc[o] = make_ulonglong2(0ULL, 0ULL);

    const float* xb = x + (size_t)n * CI * H * W * T_LEN + tc * 4;

    #pragma unroll UNR
    for (int ci = 0; ci < CI; ci++) {
        #pragma unroll
        for (int kh = 0; kh < K; kh++) {
            const int iy = oy + kh - PAD;
            const bool vy = (unsigned)iy < (unsigned)H;
            const float* xrow = xb + (size_t)(ci * H + iy) * W * T_LEN;
            #pragma unroll
            for (int kw = 0; kw < K; kw++) {
                const int ix = ox + kw - PAD;
                const bool v = vy && ((unsigned)ix < (unsigned)W);
                float4 f = make_float4(0.f, 0.f, 0.f, 0.f);
                if (v) f = *(const float4*)(xrow + (size_t)ix * T_LEN);
                ulonglong2 xu = *(ulonglong2*)&f;
                const float2* wrow = &ws[((ci * K + kh) * K + kw) * CO_BLK];
                #pragma unroll
                for (int o = 0; o < CO_BLK; o += 2) {
                    float4 wv = *(const float4*)(wrow + o);
                    ull w0 = ((ull*)&wv)[0];
                    ull w1 = ((ull*)&wv)[1];
                    acc[o].x   = ffma2(w0, xu.x, acc[o].x);
                    acc[o].y   = ffma2(w0, xu.y, acc[o].y);
                    acc[o+1].x = ffma2(w1, xu.x, acc[o+1].x);
                    acc[o+1].y = ffma2(w1, xu.y, acc[o+1].y);
                }
            }
        }
    }
    #pragma unroll
    for (int o = 0; o < CO_BLK; o++) {
        size_t off = (((size_t)(n * CO + oBase + o) * OH + oy) * OW + ox) * T_LEN
                     + tc * 4;
        *(ulonglong2*)(y + off) = acc[o];
    }
}

// ---------------------------------------------------------------------------
// Dense over (C,H,W)=3136 per timestep: [8,64,7,7,300] -> [8,10,300].
// Deeper unroll for L2-latency batching; sequential i order preserved.
// ---------------------------------------------------------------------------
__global__ __launch_bounds__(256)
void dense_kernel(const float* __restrict__ x, const float* __restrict__ wgt,
                  float* __restrict__ y) {
    int g = blockIdx.x * blockDim.x + threadIdx.x;
    if (g >= NBATCH * 10 * T_LEN) return;
    int t = g % T_LEN; int r = g / T_LEN;
    int o = r % 10;    int n = r / 10;
    const float* xb = x + (size_t)n * 3136 * T_LEN + t;
    const float* wb = wgt + o * 3136;
    float acc = 0.f;
    #pragma unroll 32
    for (int i = 0; i < 3136; i++)
        acc = fmaf(wb[i], xb[(size_t)i * T_LEN], acc);
    y[g] = acc;
}

// ---------------------------------------------------------------------------

static inline int cdiv(long long a, long long b) { return (int)((a + b - 1) / b); }

extern "C" void kernel_launch(void* const* d_in, const int* in_sizes, int n_in,
                              void* d_out, int out_size) {
    const float* in = (const float*)d_in[0];   // [8,1,30,30,300]
    const float* w1 = (const float*)d_in[1];   // [16,1,5,5]
    const float* w2 = (const float*)d_in[2];   // [32,16,3,3]
    const float* w3 = (const float*)d_in[3];   // [64,32,3,3]
    const float* w4 = (const float*)d_in[4];   // [10,64,7,7]
    float* out = (float*)d_out;                // [8,10,300]

    float *bufA, *bufB;
    cudaGetSymbolAddress((void**)&bufA, g_bufA);
    cudaGetSymbolAddress((void**)&bufB, g_bufB);

    // P0 = psp(input)  [8,1,30,30,300]
    scan_t<0><<<cdiv(7200, 128), 128>>>(in, bufA, 7200);

    // u1 = conv1(P0)   [8,16,28,28,300]
    conv_kernel<1, 16, 16, 5, 30, 30, 28, 28, 1, 1>
        <<<dim3(cdiv((long long)NBATCH * 28 * 28 * TC4, 256), 1), 256>>>(bufA, w1, bufB);

    // Q2 = psp(spike(pool(psp(spike(u1)))))  [8,16,14,14,300]
    scanpool2x<<<25088 / 128, 128>>>(bufB, bufA, 16, 14, 14);

    // u3 = conv2(Q2)   [8,32,14,14,300]
    conv_kernel<16, 32, 16, 3, 14, 14, 14, 14, 1, 2>
        <<<dim3(cdiv((long long)NBATCH * 14 * 14 * TC4, 256), 2), 256>>>(bufA, w2, bufB);

    // Q4 = psp(spike(pool(psp(spike(u3)))))  [8,32,7,7,300]
    scanpool2x<<<12544 / 128, 128>>>(bufB, bufA, 32, 7, 7);

    // u5 = conv3(Q4)   [8,64,7,7,300]
    conv_kernel<32, 64, 16, 3, 7, 7, 7, 7, 1, 2>
        <<<dim3(cdiv((long long)NBATCH * 7 * 7 * TC4, 256), 4), 256>>>(bufA, w3, bufB);

    // Q5 = psp(spike(u5))  [8,64,7,7,300]
    scan_t<1><<<cdiv(25088, 128), 128>>>(bufB, bufA, 25088);

    // u6 = dense(Q5)   [8,10,300]
    dense_kernel<<<cdiv(NBATCH * 10 * T_LEN, 256), 256>>>(bufA, w4, bufB);

    // out = spike(u6)
    scan_t<2><<<1, 128>>>(bufB, out, 80);
}

// round 13
// speedup vs baseline: 1.4884x; 1.2439x over previous
#include <cuda_runtime.h>
#include <cstddef>

// ---------------------------------------------------------------------------
// SLAYER SRM-alpha SNN — R1-bit-identical conv/scan arithmetic.
// R13 = R12 + lane-permuted conv accumulators (channel pairs in f32x2 lanes,
// undup'd weights -> 4 LDS.128/tap instead of 8) + dense split-4 (ordered
// chunk combine). Layout [N,C,H,W,T], T innermost, T=300, N=8.
// ---------------------------------------------------------------------------

#define T_LEN  300
#define TC4    75
#define NBATCH 8

typedef unsigned long long ull;

#define C_DS 0.90483741803595952f     // exp(-1/10)
#define C_B  0.27182818284590452f     // e/10
#define C_DR 0.36787944117144233f     // exp(-1)
#define C_A  (-54.365636569180902f)   // -2*10*e
#define C_TH 10.0f
#define C_POOL 11.0f

#define BUF_ELEMS 30105600
__device__ float g_bufA[BUF_ELEMS + 16];
__device__ float g_bufB[BUF_ELEMS + 16];

__device__ __forceinline__ ull ffma2(ull a, ull b, ull c) {
    ull d;
    asm("fma.rn.f32x2 %0, %1, %2, %3;" : "=l"(d) : "l"(a), "l"(b), "l"(c));
    return d;
}
__device__ __forceinline__ ull pack2(float lo, float hi) {
    return (ull)__float_as_uint(lo) | ((ull)__float_as_uint(hi) << 32);
}
__device__ __forceinline__ float lo32(ull v) { return __uint_as_float((unsigned)v); }
__device__ __forceinline__ float hi32(ull v) { return __uint_as_float((unsigned)(v >> 32)); }

#define ELT(v, k) (((k) & 3) == 0 ? (v)[(k) >> 2].x : \
                   ((k) & 3) == 1 ? (v)[(k) >> 2].y : \
                   ((k) & 3) == 2 ? (v)[(k) >> 2].z : (v)[(k) >> 2].w)

// ---------------------------------------------------------------------------
// Temporal scan, smem-free. MODE: 0=psp, 1=spike+psp, 2=spike.
// ---------------------------------------------------------------------------
template<int CL, int MODE>
__device__ __forceinline__ void scan_tile(const float* __restrict__ xr,
                                          float* __restrict__ yr,
                                          float& p_s, float& q_s,
                                          float& p_r, float& q_r) {
    constexpr int NQ = CL / 4;
    float4 v[NQ];
    #pragma unroll
    for (int q = 0; q < NQ; q++) v[q] = *(const float4*)(xr + q * 4);
    float o[CL];
    #pragma unroll
    for (int k = 0; k < CL; k++) {
        float u = ELT(v, k);
        if (MODE == 0) {
            q_s = C_DS * (q_s + p_s);
            p_s = C_DS * p_s + u;
            o[k] = C_B * q_s;
        } else {
            q_r = C_DR * (q_r + p_r);
            float vm = u + C_A * q_r;
            float s = (vm >= C_TH) ? 1.0f : 0.0f;
            p_r = C_DR * p_r + s;
            if (MODE == 1) {
                q_s = C_DS * (q_s + p_s);
                p_s = C_DS * p_s + s;
                o[k] = C_B * q_s;
            } else {
                o[k] = s;
            }
        }
    }
    #pragma unroll
    for (int q = 0; q < NQ; q++)
        *(float4*)(yr + q * 4) =
            make_float4(o[q * 4], o[q * 4 + 1], o[q * 4 + 2], o[q * 4 + 3]);
}

template<int MODE>
__global__ __launch_bounds__(128)
void scan_t(const float* __restrict__ x, float* __restrict__ y,
            int numNeurons) {
    int gn = blockIdx.x * 128 + threadIdx.x;
    if (gn >= numNeurons) return;
    const float* xr = x + (size_t)gn * T_LEN;
    float*       yr = y + (size_t)gn * T_LEN;
    float p_s = 0.f, q_s = 0.f, p_r = 0.f, q_r = 0.f;
    #pragma unroll 1
    for (int tb = 0; tb < 288; tb += 16)
        scan_tile<16, MODE>(xr + tb, yr + tb, p_s, q_s, p_r, q_r);
    scan_tile<12, MODE>(xr + 288, yr + 288, p_s, q_s, p_r, q_r);
}

// ---------------------------------------------------------------------------
// Fused [spike+psp on 4 children] + 2x2 pool(*11) + [spike+psp], smem-free.
// ---------------------------------------------------------------------------
template<int CL>
__device__ __forceinline__ void pool_tile(
    const float* __restrict__ x0, const float* __restrict__ x1,
    const float* __restrict__ x2, const float* __restrict__ x3,
    float* __restrict__ yr,
    float* cpr, float* cqr, float* cps, float* cqs,
    float& Ppr, float& Pqr, float& Pps, float& Pqs) {
    constexpr int NQ = CL / 4;
    float4 v0[NQ], v1[NQ], v2[NQ], v3[NQ];
    #pragma unroll
    for (int q = 0; q < NQ; q++) v0[q] = *(const float4*)(x0 + q * 4);
    #pragma unroll
    for (int q = 0; q < NQ; q++) v1[q] = *(const float4*)(x1 + q * 4);
    #pragma unroll
    for (int q = 0; q < NQ; q++) v2[q] = *(const float4*)(x2 + q * 4);
    #pragma unroll
    for (int q = 0; q < NQ; q++) v3[q] = *(const float4*)(x3 + q * 4);
    float o[CL];
    #pragma unroll
    for (int k = 0; k < CL; k++) {
        float outc[4];
        #pragma unroll
        for (int c = 0; c < 4; c++) {
            float u = (c == 0) ? ELT(v0, k) : (c == 1) ? ELT(v1, k)
                    : (c == 2) ? ELT(v2, k) : ELT(v3, k);
            cqr[c] = C_DR * (cqr[c] + cpr[c]);
            float vm = u + C_A * cqr[c];
            float s  = (vm >= C_TH) ? 1.0f : 0.0f;
            cpr[c] = C_DR * cpr[c] + s;
            cqs[c] = C_DS * (cqs[c] + cps[c]);
            cps[c] = C_DS * cps[c] + s;
            outc[c] = C_B * cqs[c];
        }
        float U = (outc[0] + outc[1] + outc[2] + outc[3]) * C_POOL;
        Pqr = C_DR * (Pqr + Ppr);
        float vm = U + C_A * Pqr;
        float s  = (vm >= C_TH) ? 1.0f : 0.0f;
        Ppr = C_DR * Ppr + s;
        Pqs = C_DS * (Pqs + Pps);
        Pps = C_DS * Pps + s;
        o[k] = C_B * Pqs;
    }
    #pragma unroll
    for (int q = 0; q < NQ; q++)
        *(float4*)(yr + q * 4) =
            make_float4(o[q * 4], o[q * 4 + 1], o[q * 4 + 2], o[q * 4 + 3]);
}

__global__ __launch_bounds__(128)
void scanpool2x(const float* __restrict__ x, float* __restrict__ y,
                int C, int OH, int OW) {
    const int gn = blockIdx.x * 128 + threadIdx.x;
    int ox = gn % OW; int r = gn / OW;
    int oy = r % OH;  r /= OH;
    int c  = r % C;   int n = r / C;
    const int W = OW * 2, H = OH * 2;
    size_t base = (((size_t)(n * C + c) * H + 2 * oy) * W + 2 * ox) * T_LEN;
    const float* x0 = x + base;
    const float* x1 = x + base + T_LEN;
    const float* x2 = x + base + (size_t)W * T_LEN;
    const float* x3 = x + base + (size_t)(W + 1) * T_LEN;
    float* yr = y + (size_t)gn * T_LEN;

    float cpr[4] = {0,0,0,0}, cqr[4] = {0,0,0,0};
    float cps[4] = {0,0,0,0}, cqs[4] = {0,0,0,0};
    float Ppr = 0.f, Pqr = 0.f, Pps = 0.f, Pqs = 0.f;

    #pragma unroll 1
    for (int tb = 0; tb < 288; tb += 16)
        pool_tile<16>(x0 + tb, x1 + tb, x2 + tb, x3 + tb, yr + tb,
                      cpr, cqr, cps, cqs, Ppr, Pqr, Pps, Pqs);
    pool_tile<12>(x0 + 288, x1 + 288, x2 + 288, x3 + 288, yr + 288,
                  cpr, cqr, cps, cqs, Ppr, Pqr, Pps, Pqs);
}

// ---------------------------------------------------------------------------
// Direct conv, lane-permuted accumulators. CO_BLK=16 channels as 8 f32x2
// channel-pairs; weights undup'd in smem (4 LDS.128/tap). Four accs per
// channel-pair fed with (x0,x1),(x1,x0),(x2,x3),(x3,x2) so every f32x2 lane
// keeps a fixed (channel,t) identity; accumulation order per output value is
// (ci,kh,kw) — R1-identical. Boundary taps are predicated zero-fill loads
// (fma(w,0,acc) == acc exactly).
// ---------------------------------------------------------------------------
template<int CI, int CO, int CO_BLK, int K, int H, int W, int OH, int OW,
         int PAD, int UNR>
__global__ __launch_bounds__(256, 2)
void conv_kernel(const float* __restrict__ x, const float* __restrict__ wgt,
                 float* __restrict__ y) {
    constexpr int TAPS = CI * K * K;
    constexpr int NP = CO_BLK / 2;              // channel pairs
    __shared__ float2 ws[TAPS * NP];            // (w_o, w_{o+1}) per tap
    const int oBase = blockIdx.y * CO_BLK;
    for (int i = threadIdx.x; i < TAPS * NP; i += blockDim.x) {
        int p = i % NP, tap = i / NP;
        ws[i] = make_float2(wgt[(oBase + 2 * p) * TAPS + tap],
                            wgt[(oBase + 2 * p + 1) * TAPS + tap]);
    }
    __syncthreads();

    long long g = (long long)blockIdx.x * blockDim.x + threadIdx.x;
    int tc = (int)(g % TC4); long long r = g / TC4;
    int ox = (int)(r % OW); r /= OW;
    int oy = (int)(r % OH); r /= OH;
    int n  = (int)r;
    if (n >= NBATCH) return;

    // accs: per pair p, lanes are A:(o,t0|o1,t1) B:(o,t1|o1,t0)
    //                              C:(o,t2|o1,t3) D:(o,t3|o1,t2)
    ull A[NP], B[NP], C[NP], D[NP];
    #pragma unroll
    for (int p = 0; p < NP; p++) { A[p] = 0; B[p] = 0; C[p] = 0; D[p] = 0; }

    const float* xb = x + (size_t)n * CI * H * W * T_LEN + tc * 4;

    #pragma unroll UNR
    for (int ci = 0; ci < CI; ci++) {
        #pragma unroll
        for (int kh = 0; kh < K; kh++) {
            const int iy = oy + kh - PAD;
            const bool vy = (unsigned)iy < (unsigned)H;
            const float* xrow = xb + (size_t)(ci * H + iy) * W * T_LEN;
            #pragma unroll
            for (int kw = 0; kw < K; kw++) {
                const int ix = ox + kw - PAD;
                const bool v = vy && ((unsigned)ix < (unsigned)W);
                float4 f = make_float4(0.f, 0.f, 0.f, 0.f);
                if (v) f = *(const float4*)(xrow + (size_t)ix * T_LEN);
                const ull x01 = ((const ull*)&f)[0];
                const ull x23 = ((const ull*)&f)[1];
                const ull x10 = pack2(f.y, f.x);
                const ull x32 = pack2(f.w, f.z);
                const float2* wrow = &ws[((ci * K + kh) * K + kw) * NP];
                #pragma unroll
                for (int p = 0; p < NP; p += 2) {
                    float4 wv = *(const float4*)(wrow + p);
                    ull w0 = ((ull*)&wv)[0];
                    ull w1 = ((ull*)&wv)[1];
                    A[p]   = ffma2(w0, x01, A[p]);
                    B[p]   = ffma2(w0, x10, B[p]);
                    C[p]   = ffma2(w0, x23, C[p]);
                    D[p]   = ffma2(w0, x32, D[p]);
                    A[p+1] = ffma2(w1, x01, A[p+1]);
                    B[p+1] = ffma2(w1, x10, B[p+1]);
                    C[p+1] = ffma2(w1, x23, C[p+1]);
                    D[p+1] = ffma2(w1, x32, D[p+1]);
                }
            }
        }
    }
    const size_t chstr = (size_t)OH * OW * T_LEN;
    size_t off0 = (((size_t)(n * CO + oBase) * OH + oy) * OW + ox) * T_LEN + tc * 4;
    #pragma unroll
    for (int p = 0; p < NP; p++) {
        *(float4*)(y + off0 + (size_t)(2 * p) * chstr) =
            make_float4(lo32(A[p]), lo32(B[p]), lo32(C[p]), lo32(D[p]));
        *(float4*)(y + off0 + (size_t)(2 * p + 1) * chstr) =
            make_float4(hi32(B[p]), hi32(A[p]), hi32(D[p]), hi32(C[p]));
    }
}

// ---------------------------------------------------------------------------
// Dense split-4: partials over i-chunks of 784 (each internally sequential),
// then ordered combine ((P0+P1)+P2)+P3.  x [8,64,7,7,300] -> u6 [8,10,300].
// ---------------------------------------------------------------------------
#define DOUT (NBATCH * 10 * T_LEN)     // 24000
#define DCHUNK 784                     // 3136 / 4

__global__ __launch_bounds__(256)
void dense_part(const float* __restrict__ x, const float* __restrict__ wgt,
                float* __restrict__ part) {
    int g = blockIdx.x * blockDim.x + threadIdx.x;
    if (g >= DOUT * 4) return;
    int c = g / DOUT;  int gg = g % DOUT;
    int t = gg % T_LEN; int r = gg / T_LEN;
    int o = r % 10;     int n = r / 10;
    const float* xb = x + (size_t)n * 3136 * T_LEN + (size_t)(c * DCHUNK) * T_LEN + t;
    const float* wb = wgt + o * 3136 + c * DCHUNK;
    float acc = 0.f;
    #pragma unroll 28
    for (int i = 0; i < DCHUNK; i++)
        acc = fmaf(wb[i], xb[(size_t)i * T_LEN], acc);
    part[g] = acc;
}

__global__ __launch_bounds__(256)
void dense_combine(const float* __restrict__ part, float* __restrict__ y) {
    int g = blockIdx.x * blockDim.x + threadIdx.x;
    if (g >= DOUT) return;
    float s = part[g];
    s = s + part[DOUT + g];
    s = s + part[2 * DOUT + g];
    s = s + part[3 * DOUT + g];
    y[g] = s;
}

// ---------------------------------------------------------------------------

static inline int cdiv(long long a, long long b) { return (int)((a + b - 1) / b); }

extern "C" void kernel_launch(void* const* d_in, const int* in_sizes, int n_in,
                              void* d_out, int out_size) {
    const float* in = (const float*)d_in[0];   // [8,1,30,30,300]
    const float* w1 = (const float*)d_in[1];   // [16,1,5,5]
    const float* w2 = (const float*)d_in[2];   // [32,16,3,3]
    const float* w3 = (const float*)d_in[3];   // [64,32,3,3]
    const float* w4 = (const float*)d_in[4];   // [10,64,7,7]
    float* out = (float*)d_out;                // [8,10,300]

    float *bufA, *bufB;
    cudaGetSymbolAddress((void**)&bufA, g_bufA);
    cudaGetSymbolAddress((void**)&bufB, g_bufB);

    // P0 = psp(input)  [8,1,30,30,300]
    scan_t<0><<<cdiv(7200, 128), 128>>>(in, bufA, 7200);

    // u1 = conv1(P0)   [8,16,28,28,300]
    conv_kernel<1, 16, 16, 5, 30, 30, 28, 28, 1, 1>
        <<<dim3(cdiv((long long)NBATCH * 28 * 28 * TC4, 256), 1), 256>>>(bufA, w1, bufB);

    // Q2 = psp(spike(pool(psp(spike(u1)))))  [8,16,14,14,300]
    scanpool2x<<<25088 / 128, 128>>>(bufB, bufA, 16, 14, 14);

    // u3 = conv2(Q2)   [8,32,14,14,300]
    conv_kernel<16, 32, 16, 3, 14, 14, 14, 14, 1, 2>
        <<<dim3(cdiv((long long)NBATCH * 14 * 14 * TC4, 256), 2), 256>>>(bufA, w2, bufB);

    // Q4 = psp(spike(pool(psp(spike(u3)))))  [8,32,7,7,300]
    scanpool2x<<<12544 / 128, 128>>>(bufB, bufA, 32, 7, 7);

    // u5 = conv3(Q4)   [8,64,7,7,300]
    conv_kernel<32, 64, 16, 3, 7, 7, 7, 7, 1, 2>
        <<<dim3(cdiv((long long)NBATCH * 7 * 7 * TC4, 256), 4), 256>>>(bufA, w3, bufB);

    // Q5 = psp(spike(u5))  [8,64,7,7,300]
    scan_t<1><<<cdiv(25088, 128), 128>>>(bufB, bufA, 25088);

    // u6 = dense(Q5): partials + ordered combine
    float* part = bufB + 65536;
    dense_part<<<cdiv(DOUT * 4, 256), 256>>>(bufA, w4, part);
    dense_combine<<<cdiv(DOUT, 256), 256>>>(part, bufB);

    // out = spike(u6)
    scan_t<2><<<1, 128>>>(bufB, out, 80);
}